// round 10
// baseline (speedup 1.0000x reference)
#include <cuda_runtime.h>
#include <cuda_bf16.h>
#include <cstdint>

#define T_ 128
#define B_ 512
#define D_ 768
#define R_ (T_*B_)   // 65536 rows

typedef unsigned long long ull;

// ---------------- scratch (static device globals; no allocation) ----------------
__device__ __align__(16) float g_xproj[R_ * 64];  // [t][b][dir][u][4] : col = dir*32 + u*4 + gate
__device__ __align__(16) float g_h[R_ * 16];      // [t][b][16]: 0..7 fwd h, 8..15 bwd h
__device__ __align__(16) float g_zproj[R_ * 64];  // [t][b][u][4]
__device__ __align__(16) float g_z[R_ * 16];      // ptr-LSTM hidden states
__device__ __align__(16) __nv_bfloat16 g_eb[(size_t)T_ * B_ * B_];  // exp(S) cache, 67MB
__device__ int g_dummy;

// ---------------- helpers ----------------
__device__ __forceinline__ ull ffma2(ull a, ull b, ull c) {
    ull d;
    asm("fma.rn.f32x2 %0, %1, %2, %3;" : "=l"(d) : "l"(a), "l"(b), "l"(c));
    return d;
}
__device__ __forceinline__ ull add2(ull a, ull b) {
    ull d;
    asm("add.rn.f32x2 %0, %1, %2;" : "=l"(d) : "l"(a), "l"(b));
    return d;
}
__device__ __forceinline__ ull pack2(float lo, float hi) {
    ull r;
    asm("mov.b64 %0, {%1, %2};" : "=l"(r) : "f"(lo), "f"(hi));
    return r;
}
__device__ __forceinline__ float2 unpack2(ull v) {
    float lo, hi;
    asm("mov.b64 {%0, %1}, %2;" : "=f"(lo), "=f"(hi) : "l"(v));
    return make_float2(lo, hi);
}
// HW tanh (MUFU.TANH, sm_75+): single op on the critical path.
__device__ __forceinline__ float tanh_hw(float x) {
    float y;
    asm("tanh.approx.f32 %0, %1;" : "=f"(y) : "f"(x));
    return y;
}
// sigmoid via HW tanh: sigmoid(x) = 0.5*tanh(x/2) + 0.5
__device__ __forceinline__ float sigm_hw(float x) {
    return __fmaf_rn(0.5f, tanh_hw(0.5f * x), 0.5f);
}
__device__ __forceinline__ float ex2(float x) {
    float y;
    asm("ex2.approx.f32 %0, %1;" : "=f"(y) : "f"(x));
    return y;
}
__device__ __forceinline__ uint32_t smem_u32(const void* p) {
    uint32_t a;
    asm("{ .reg .u64 t; cvta.to.shared.u64 t, %1; cvt.u32.u64 %0, t; }" : "=r"(a) : "l"(p));
    return a;
}

// map output column c (0..63) of the big projection to the original W row.
__device__ __forceinline__ int bi_row_of_col(int c, int& dir) {
    dir = c >> 5;
    int w = c & 31;
    return (w & 3) * 8 + (w >> 2);
}

// ---------------- dummy (shifts the ncu -s5 capture window onto proj) ----------------
__global__ void dummy_kernel(int v) {
    if (threadIdx.x == 1025u) g_dummy = v;   // never true (32-thread launch)
}

// ---------------- warp MMA (HMMA, plain PTX — works on bare sm_103) ----------------
__device__ __forceinline__ void mma_bf16(float* c, const uint32_t* a, uint32_t b0, uint32_t b1) {
    asm volatile(
        "mma.sync.aligned.m16n8k16.row.col.f32.bf16.bf16.f32 "
        "{%0,%1,%2,%3}, {%4,%5,%6,%7}, {%8,%9}, {%0,%1,%2,%3};"
        : "+f"(c[0]), "+f"(c[1]), "+f"(c[2]), "+f"(c[3])
        : "r"(a[0]), "r"(a[1]), "r"(a[2]), "r"(a[3]), "r"(b0), "r"(b1));
}
__device__ __forceinline__ void ldm4(uint32_t* r, uint32_t addr) {
    asm volatile("ldmatrix.sync.aligned.m8n8.x4.shared.b16 {%0,%1,%2,%3}, [%4];"
                 : "=r"(r[0]), "=r"(r[1]), "=r"(r[2]), "=r"(r[3]) : "r"(addr));
}

// ---------------- K1: HMMA projection GEMM ----------------
#define PA_HI 0
#define PA_LO 16384
#define PB_HI 32768
#define PB_LO 40960
#define PROJ_SMEM 49152
#define NKC 12

__device__ __forceinline__ void cvt_hilo8(float4 v0, float4 v1, uint4& hi, uint4& lo) {
    float xs[8] = {v0.x, v0.y, v0.z, v0.w, v1.x, v1.y, v1.z, v1.w};
    uint32_t h[4], l[4];
    #pragma unroll
    for (int i = 0; i < 4; i++) {
        float a = xs[2 * i], b = xs[2 * i + 1];
        uint32_t hp;
        asm("cvt.rn.bf16x2.f32 %0, %1, %2;" : "=r"(hp) : "f"(b), "f"(a));
        float fa = __uint_as_float(hp << 16);
        float fb = __uint_as_float(hp & 0xffff0000u);
        float la = a - fa, lb = b - fb;
        uint32_t lp;
        asm("cvt.rn.bf16x2.f32 %0, %1, %2;" : "=r"(lp) : "f"(lb), "f"(la));
        h[i] = hp; l[i] = lp;
    }
    hi = make_uint4(h[0], h[1], h[2], h[3]);
    lo = make_uint4(l[0], l[1], l[2], l[3]);
}

__global__ void __launch_bounds__(256) proj_mma_kernel(
    const float* __restrict__ X,
    const float* __restrict__ Wf, const float* __restrict__ Wb,
    const float* __restrict__ bif, const float* __restrict__ bhf,
    const float* __restrict__ bib, const float* __restrict__ bhb)
{
    extern __shared__ __align__(1024) char psm[];
    __shared__ float bias[64];
    const uint32_t smem_base = smem_u32(psm);
    const int tid = threadIdx.x;
    const int w = tid >> 5, lane = tid & 31;
    const int row0 = blockIdx.x * 128;

    if (tid < 64) {
        int dir;
        int r = bi_row_of_col(tid, dir);
        bias[tid] = dir ? (bib[r] + bhb[r]) : (bif[r] + bhf[r]);
    }

    const int rowA = 16 * w + (lane & 15);
    const uint32_t aRow = smem_base + rowA * 128;
    const uint32_t axr = (rowA & 7) << 4;
    const uint32_t akoff = (lane >= 16) ? 16u : 0u;

    const int nB = (lane & 7) + ((lane >> 4) << 3);
    const uint32_t bxr = (lane & 7) << 4;
    const uint32_t bkoff = (lane & 8) ? 16u : 0u;

    float acc[32];
    #pragma unroll
    for (int i = 0; i < 32; i++) acc[i] = 0.f;

    for (int kc = 0; kc < NKC; kc++) {
        const int k0 = kc * 64;
        float4 areg[8], breg[4];
        #pragma unroll
        for (int q = 0; q < 4; q++) {
            int unit = tid + q * 256;
            int r = unit >> 3, c8 = unit & 7;
            const float* p = X + (size_t)(row0 + r) * D_ + k0 + c8 * 8;
            areg[2 * q]     = *(const float4*)p;
            areg[2 * q + 1] = *(const float4*)(p + 4);
        }
        #pragma unroll
        for (int q = 0; q < 2; q++) {
            int unit = tid + q * 256;
            int n = unit >> 3, c8 = unit & 7;
            int dir;
            int rr = bi_row_of_col(n, dir);
            const float* p = (dir ? Wb : Wf) + rr * D_ + k0 + c8 * 8;
            breg[2 * q]     = *(const float4*)p;
            breg[2 * q + 1] = *(const float4*)(p + 4);
        }
        __syncthreads();

        #pragma unroll
        for (int q = 0; q < 4; q++) {
            int unit = tid + q * 256;
            int r = unit >> 3, c8 = unit & 7;
            uint32_t off = r * 128 + c8 * 16;
            uint32_t sw = off ^ ((off >> 3) & 0x70);
            uint4 hi, lo;
            cvt_hilo8(areg[2 * q], areg[2 * q + 1], hi, lo);
            *(uint4*)(psm + PA_HI + sw) = hi;
            *(uint4*)(psm + PA_LO + sw) = lo;
        }
        #pragma unroll
        for (int q = 0; q < 2; q++) {
            int unit = tid + q * 256;
            int n = unit >> 3, c8 = unit & 7;
            uint32_t off = n * 128 + c8 * 16;
            uint32_t sw = off ^ ((off >> 3) & 0x70);
            uint4 hi, lo;
            cvt_hilo8(breg[2 * q], breg[2 * q + 1], hi, lo);
            *(uint4*)(psm + PB_HI + sw) = hi;
            *(uint4*)(psm + PB_LO + sw) = lo;
        }
        __syncthreads();

        #pragma unroll
        for (int ks = 0; ks < 4; ks++) {
            const uint32_t ak = (ks * 32 + akoff) ^ axr;
            uint32_t ahi[4], alo[4];
            ldm4(ahi, aRow + PA_HI + ak);
            ldm4(alo, aRow + PA_LO + ak);
            #pragma unroll
            for (int np = 0; np < 4; np++) {
                const int n = np * 16 + nB;
                const uint32_t bk = (uint32_t)n * 128 + ((ks * 32 + bkoff) ^ bxr);
                uint32_t bhi[4], blo[4];
                ldm4(bhi, smem_base + PB_HI + bk);
                ldm4(blo, smem_base + PB_LO + bk);
                float* c0 = acc + (2 * np) * 4;
                float* c1 = acc + (2 * np + 1) * 4;
                mma_bf16(c0, ahi, bhi[0], bhi[1]);
                mma_bf16(c0, ahi, blo[0], blo[1]);
                mma_bf16(c0, alo, bhi[0], bhi[1]);
                mma_bf16(c1, ahi, bhi[2], bhi[3]);
                mma_bf16(c1, ahi, blo[2], blo[3]);
                mma_bf16(c1, alo, bhi[2], bhi[3]);
            }
        }
    }

    const int g = lane >> 2, tq = (lane & 3) * 2;
    const int r0 = row0 + 16 * w + g;
    #pragma unroll
    for (int nt = 0; nt < 8; nt++) {
        int col = nt * 8 + tq;
        float b0 = bias[col], b1 = bias[col + 1];
        float* d0 = g_xproj + (size_t)r0 * 64 + col;
        float* d1 = g_xproj + (size_t)(r0 + 8) * 64 + col;
        *(float2*)d0 = make_float2(acc[nt * 4 + 0] + b0, acc[nt * 4 + 1] + b1);
        *(float2*)d1 = make_float2(acc[nt * 4 + 2] + b0, acc[nt * 4 + 3] + b1);
    }
}

// ---------------- scan dot helpers (packed h in registers) ----------------
__device__ __forceinline__ float dot8p(ull h01, ull h23, ull h45, ull h67,
                                       ulonglong2 w01, ulonglong2 w23, float x) {
    ull a0 = ffma2(h45, w23.x, ffma2(h01, w01.x, 0ULL));
    ull a1 = ffma2(h67, w23.y, ffma2(h23, w01.y, 0ULL));
    float2 v = unpack2(add2(a0, a1));
    return x + v.x + v.y;
}
__device__ __forceinline__ float dot16p(const ull* hp, const ulonglong2* w, float x) {
    ull a0 = ffma2(hp[4], w[2].x, ffma2(hp[0], w[0].x, 0ULL));
    ull a1 = ffma2(hp[5], w[2].y, ffma2(hp[1], w[0].y, 0ULL));
    ull a2 = ffma2(hp[6], w[3].x, ffma2(hp[2], w[1].x, 0ULL));
    ull a3 = ffma2(hp[7], w[3].y, ffma2(hp[3], w[1].y, 0ULL));
    float2 v = unpack2(add2(add2(a0, a1), add2(a2, a3)));
    return x + v.x + v.y;
}

// ---------------- K2: bidirectional LSTM scan (H=8) ----------------
// grid (64, 2), 64 threads = 8 elems x 8 units. Weights in registers,
// h-exchange via shfl (no smem round trip). Loop MUST stay unrolled x4.
__global__ void __launch_bounds__(64) lstm_bi_kernel(
    const float* __restrict__ Whhf, const float* __restrict__ Whhb)
{
    const int tid = threadIdx.x;
    const int dir = blockIdx.y;
    const int e = tid >> 3, u = tid & 7;
    const int b = blockIdx.x * 8 + e;
    const int base = tid & 24;   // lane-group base within warp

    const float* W = dir ? Whhb : Whhf;
    ulonglong2 wi0 = *(const ulonglong2*)(W + u * 8);
    ulonglong2 wi1 = *(const ulonglong2*)(W + u * 8 + 4);
    ulonglong2 wf0 = *(const ulonglong2*)(W + (8 + u) * 8);
    ulonglong2 wf1 = *(const ulonglong2*)(W + (8 + u) * 8 + 4);
    ulonglong2 wg0 = *(const ulonglong2*)(W + (16 + u) * 8);
    ulonglong2 wg1 = *(const ulonglong2*)(W + (16 + u) * 8 + 4);
    ulonglong2 wo0 = *(const ulonglong2*)(W + (24 + u) * 8);
    ulonglong2 wo1 = *(const ulonglong2*)(W + (24 + u) * 8 + 4);

    float hv[8];
    #pragma unroll
    for (int j = 0; j < 8; j++) hv[j] = 0.f;
    float cu = 0.f;

    const float4* xsrc = (const float4*)g_xproj;
    const long long stride4 = (long long)B_ * 16;
    const long long step = dir ? -stride4 : stride4;
    long long idx = ((long long)(dir ? T_ - 1 : 0) * B_ + b) * 16 + dir * 8 + u;
    float4 buf[4];
    #pragma unroll
    for (int p = 0; p < 4; p++) buf[p] = xsrc[idx + p * step];

    float* hp0 = g_h + (size_t)b * 16 + dir * 8 + u;

    #pragma unroll 4
    for (int s = 0; s < T_; s++) {
        const int tt = dir ? (T_ - 1 - s) : s;
        float4 x = buf[s & 3];
        if (s + 4 < T_) buf[s & 3] = xsrc[idx + (long long)(s + 4) * step];

        ull h01 = pack2(hv[0], hv[1]), h23 = pack2(hv[2], hv[3]);
        ull h45 = pack2(hv[4], hv[5]), h67 = pack2(hv[6], hv[7]);

        float gi = dot8p(h01, h23, h45, h67, wi0, wi1, x.x);
        float gf = dot8p(h01, h23, h45, h67, wf0, wf1, x.y);
        float gg = dot8p(h01, h23, h45, h67, wg0, wg1, x.z);
        float go = dot8p(h01, h23, h45, h67, wo0, wo1, x.w);

        float ii = sigm_hw(gi), ff = sigm_hw(gf);
        float g2 = tanh_hw(gg), oo = sigm_hw(go);
        cu = __fmaf_rn(ff, cu, ii * g2);
        float hu = oo * tanh_hw(cu);
        #pragma unroll
        for (int j = 0; j < 8; j++)
            hv[j] = __shfl_sync(0xffffffffu, hu, base + j);
        hp0[(size_t)tt * (B_ * 16)] = hu;
    }
}

// ---------------- K3: ptr-LSTM input projection (gate-interleaved output) -------
__global__ void __launch_bounds__(256) zproj_kernel(
    const float* __restrict__ Wihp, const float* __restrict__ bip,
    const float* __restrict__ bhp)
{
    __shared__ float W[64][16];
    __shared__ float bias[64];
    const int tid = threadIdx.x;
    #pragma unroll
    for (int i = tid; i < 1024; i += 256) {
        int n = i >> 4, k = i & 15;
        int u = n >> 2, g = n & 3;
        W[n][k] = Wihp[(g * 16 + u) * 16 + k];
    }
    if (tid < 64) {
        int u = tid >> 2, g = tid & 3;
        int r = g * 16 + u;
        bias[tid] = bip[r] + bhp[r];
    }
    __syncthreads();

    size_t r = (size_t)blockIdx.x * 256 + tid;
    const float4* h4 = (const float4*)(g_h + r * 16);
    float4 a0 = h4[0], a1 = h4[1], a2 = h4[2], a3 = h4[3];
    float hr[16] = {a0.x, a0.y, a0.z, a0.w, a1.x, a1.y, a1.z, a1.w,
                    a2.x, a2.y, a2.z, a2.w, a3.x, a3.y, a3.z, a3.w};
    float* out = g_zproj + r * 64;
    #pragma unroll
    for (int g0 = 0; g0 < 64; g0 += 4) {
        float o[4];
        #pragma unroll
        for (int q = 0; q < 4; q++) {
            int g = g0 + q;
            float a = bias[g];
            #pragma unroll
            for (int k = 0; k < 16; k++) a = __fmaf_rn(W[g][k], hr[k], a);
            o[q] = a;
        }
        *(float4*)(out + g0) = make_float4(o[0], o[1], o[2], o[3]);
    }
}

// ---------------- K4: ptr LSTM scan (H=16) ----------------
// grid 128, 64 threads = 4 elems x 16 units. Weights in registers,
// shfl h-exchange, f32x2 dot chains, HW tanh. Loop stays unrolled x4.
__global__ void __launch_bounds__(64) lstm_ptr_kernel(const float* __restrict__ Whhp)
{
    const int tid = threadIdx.x;
    const int e = tid >> 4, u = tid & 15;
    const int b = blockIdx.x * 4 + e;
    const int base = tid & 16;

    ulonglong2 wi[4], wf4[4], wg4[4], wo4[4];
    {
        const ulonglong2* p;
        p = (const ulonglong2*)(Whhp + u * 16);
        wi[0] = p[0]; wi[1] = p[1]; wi[2] = p[2]; wi[3] = p[3];
        p = (const ulonglong2*)(Whhp + (16 + u) * 16);
        wf4[0] = p[0]; wf4[1] = p[1]; wf4[2] = p[2]; wf4[3] = p[3];
        p = (const ulonglong2*)(Whhp + (32 + u) * 16);
        wg4[0] = p[0]; wg4[1] = p[1]; wg4[2] = p[2]; wg4[3] = p[3];
        p = (const ulonglong2*)(Whhp + (48 + u) * 16);
        wo4[0] = p[0]; wo4[1] = p[1]; wo4[2] = p[2]; wo4[3] = p[3];
    }

    float hv[16];
    #pragma unroll
    for (int j = 0; j < 16; j++) hv[j] = 0.f;
    float cu = 0.f;

    const float4* zsrc = (const float4*)g_zproj;
    const long long stride4 = (long long)B_ * 16;
    long long idx = (long long)b * 16 + u;
    float4 buf[4];
    #pragma unroll
    for (int p = 0; p < 4; p++) buf[p] = zsrc[idx + p * stride4];

    float* zp0 = g_z + (size_t)b * 16 + u;

    #pragma unroll 4
    for (int t = 0; t < T_; t++) {
        float4 x = buf[t & 3];
        if (t + 4 < T_) buf[t & 3] = zsrc[idx + (long long)(t + 4) * stride4];

        ull hp[8];
        #pragma unroll
        for (int j = 0; j < 8; j++) hp[j] = pack2(hv[2 * j], hv[2 * j + 1]);

        float gi = dot16p(hp, wi,  x.x);
        float gf = dot16p(hp, wf4, x.y);
        float gg = dot16p(hp, wg4, x.z);
        float go = dot16p(hp, wo4, x.w);

        float ii = sigm_hw(gi), ff = sigm_hw(gf);
        float g2 = tanh_hw(gg), oo = sigm_hw(go);
        cu = __fmaf_rn(ff, cu, ii * g2);
        float hu = oo * tanh_hw(cu);
        #pragma unroll
        for (int j = 0; j < 16; j++)
            hv[j] = __shfl_sync(0xffffffffu, hu, base + j);
        zp0[(size_t)t * (B_ * 16)] = hu;
    }
}

// ---------------- K5: fused attention + output head, one CTA per t ----------------
#define ATT_SMEM_FLOATS (8192 + 512 + 256 + 256 + 16)
__global__ void __launch_bounds__(512) attn_kernel(
    const float* __restrict__ W_h, const float* __restrict__ W_e,
    const float* __restrict__ W_v, float* __restrict__ out)
{
    extern __shared__ __align__(16) float sm[];
    float* hs   = sm;            // 512 x 16
    float* cinv = sm + 8192;     // 512
    float* whs  = sm + 8704;     // 16 x 16
    float* wes  = sm + 8960;     // 16 x 16
    float* wvs  = sm + 9216;     // 16

    const int tid = threadIdx.x;
    const int t = blockIdx.x;
    {
        const float4* hsrc = (const float4*)(g_h + (size_t)t * (B_ * 16));
        float4* hd = (float4*)hs;
        #pragma unroll
        for (int i = 0; i < 4; i++) hd[tid + i * 512] = hsrc[tid + i * 512];
    }
    if (tid < 256) { whs[tid] = W_h[tid]; wes[tid] = W_e[tid]; }
    if (tid < 16)  wvs[tid] = W_v[tid];
    __syncthreads();

    // ---- pass 1: thread c owns column c -> exp store + colsum ----
    {
        const float L2E = 1.44269504f;
        const float4* zg = (const float4*)(g_z + (size_t)t * (B_ * 16) + (size_t)tid * 16);
        float4 z0 = zg[0], z1 = zg[1], z2 = zg[2], z3 = zg[3];
        ull zq[8];
        zq[0] = pack2(z0.x * L2E, z0.y * L2E); zq[1] = pack2(z0.z * L2E, z0.w * L2E);
        zq[2] = pack2(z1.x * L2E, z1.y * L2E); zq[3] = pack2(z1.z * L2E, z1.w * L2E);
        zq[4] = pack2(z2.x * L2E, z2.y * L2E); zq[5] = pack2(z2.z * L2E, z2.w * L2E);
        zq[6] = pack2(z3.x * L2E, z3.y * L2E); zq[7] = pack2(z3.z * L2E, z3.w * L2E);

        __nv_bfloat16* ecol = g_eb + (size_t)t * B_ * B_ + tid;
        float colsum = 0.f;
        #pragma unroll 2
        for (int bb = 0; bb < B_; bb++) {
            const ulonglong2* hr = (const ulonglong2*)(hs + bb * 16);
            ulonglong2 hq0 = hr[0], hq1 = hr[1], hq2 = hr[2], hq3 = hr[3];
            ull aA = 0ULL, aB = 0ULL;
            aA = ffma2(hq0.x, zq[0], aA); aB = ffma2(hq0.y, zq[1], aB);
            aA = ffma2(hq1.x, zq[2], aA); aB = ffma2(hq1.y, zq[3], aB);
            aA = ffma2(hq2.x, zq[4], aA); aB = ffma2(hq2.y, zq[5], aB);
            aA = ffma2(hq3.x, zq[6], aA); aB = ffma2(hq3.y, zq[7], aB);
            float2 va = unpack2(aA), vb = unpack2(aB);
            float S = (va.x + va.y) + (vb.x + vb.y);
            float e = ex2(S);
            __nv_bfloat16 eb = __float2bfloat16(e);
            ecol[(size_t)bb * B_] = eb;
            colsum += __bfloat162float(eb);
        }
        cinv[tid] = __fdividef(1.f, colsum);
    }
    __syncthreads();

    // ---- pass 2 + output head: thread b owns row b (double-buffered loads) ----
    {
        ull cacc[8];
        #pragma unroll
        for (int k = 0; k < 8; k++) cacc[k] = 0ULL;

        const __nv_bfloat16* erow = g_eb + (size_t)t * B_ * B_ + (size_t)tid * B_;
        uint4 ev = *(const uint4*)(erow);
        float4 ci0 = *(const float4*)(cinv);
        float4 ci1 = *(const float4*)(cinv + 4);
        for (int c0 = 0; c0 < B_; c0 += 8) {
            uint4 evn; float4 cin0, cin1;
            if (c0 + 8 < B_) {
                evn  = *(const uint4*)(erow + c0 + 8);
                cin0 = *(const float4*)(cinv + c0 + 8);
                cin1 = *(const float4*)(cinv + c0 + 12);
            }
            uint32_t uu[4] = {ev.x, ev.y, ev.z, ev.w};
            float cis[8] = {ci0.x, ci0.y, ci0.z, ci0.w, ci1.x, ci1.y, ci1.z, ci1.w};
            #pragma unroll
            for (int k = 0; k < 4; k++) {
                float e0 = __uint_as_float(uu[k] << 16);
                float e1 = __uint_as_float(uu[k] & 0xffff0000u);
                float w0 = e0 * cis[2 * k];
                float w1 = e1 * cis[2 * k + 1];
                {
                    ull w2 = pack2(w0, w0);
                    const ulonglong2* hc = (const ulonglong2*)(hs + (c0 + 2 * k) * 16);
                    ulonglong2 q0 = hc[0], q1 = hc[1], q2 = hc[2], q3 = hc[3];
                    cacc[0] = ffma2(q0.x, w2, cacc[0]); cacc[1] = ffma2(q0.y, w2, cacc[1]);
                    cacc[2] = ffma2(q1.x, w2, cacc[2]); cacc[3] = ffma2(q1.y, w2, cacc[3]);
                    cacc[4] = ffma2(q2.x, w2, cacc[4]); cacc[5] = ffma2(q2.y, w2, cacc[5]);
                    cacc[6] = ffma2(q3.x, w2, cacc[6]); cacc[7] = ffma2(q3.y, w2, cacc[7]);
                }
                {
                    ull w2 = pack2(w1, w1);
                    const ulonglong2* hc = (const ulonglong2*)(hs + (c0 + 2 * k + 1) * 16);
                    ulonglong2 q0 = hc[0], q1 = hc[1], q2 = hc[2], q3 = hc[3];
                    cacc[0] = ffma2(q0.x, w2, cacc[0]); cacc[1] = ffma2(q0.y, w2, cacc[1]);
                    cacc[2] = ffma2(q1.x, w2, cacc[2]); cacc[3] = ffma2(q1.y, w2, cacc[3]);
                    cacc[4] = ffma2(q2.x, w2, cacc[4]); cacc[5] = ffma2(q2.y, w2, cacc[5]);
                    cacc[6] = ffma2(q3.x, w2, cacc[6]); cacc[7] = ffma2(q3.y, w2, cacc[7]);
                }
            }
            ev = evn; ci0 = cin0; ci1 = cin1;
        }

        float ctxv[16], hbv[16];
        #pragma unroll
        for (int k = 0; k < 8; k++) {
            float2 v = unpack2(cacc[k]);
            ctxv[2 * k] = v.x; ctxv[2 * k + 1] = v.y;
        }
        {
            const float4* hb4 = (const float4*)(hs + tid * 16);
            float4 a0 = hb4[0], a1 = hb4[1], a2 = hb4[2], a3 = hb4[3];
            hbv[0] = a0.x;  hbv[1] = a0.y;  hbv[2] = a0.z;  hbv[3] = a0.w;
            hbv[4] = a1.x;  hbv[5] = a1.y;  hbv[6] = a1.z;  hbv[7] = a1.w;
            hbv[8] = a2.x;  hbv[9] = a2.y;  hbv[10] = a2.z; hbv[11] = a2.w;
            hbv[12] = a3.x; hbv[13] = a3.y; hbv[14] = a3.z; hbv[15] = a3.w;
        }
        float pacc = 0.f;
        #pragma unroll
        for (int d = 0; d < 16; d++) {
            float a = 0.f;
            #pragma unroll
            for (int k = 0; k < 16; k++) a = __fmaf_rn(whs[d * 16 + k], hbv[k], a);
            #pragma unroll
            for (int k = 0; k < 16; k++) a = __fmaf_rn(wes[d * 16 + k], ctxv[k], a);
            float ud = tanh_hw(a);
            pacc = __fmaf_rn(ud, wvs[d], pacc);
        }
        out[(size_t)t * B_ + tid] = sigm_hw(pacc);
    }
}

// ---------------- launch ----------------
extern "C" void kernel_launch(void* const* d_in, const int* in_sizes, int n_in,
                              void* d_out, int out_size)
{
    (void)in_sizes; (void)n_in; (void)out_size;
    const float* X     = (const float*)d_in[0];
    const float* Wih_f = (const float*)d_in[1];
    const float* Whh_f = (const float*)d_in[2];
    const float* bih_f = (const float*)d_in[3];
    const float* bhh_f = (const float*)d_in[4];
    const float* Wih_b = (const float*)d_in[5];
    const float* Whh_b = (const float*)d_in[6];
    const float* bih_b = (const float*)d_in[7];
    const float* bhh_b = (const float*)d_in[8];
    const float* Wih_p = (const float*)d_in[9];
    const float* Whh_p = (const float*)d_in[10];
    const float* bih_p = (const float*)d_in[11];
    const float* bhh_p = (const float*)d_in[12];
    const float* W_h   = (const float*)d_in[13];
    const float* W_e   = (const float*)d_in[14];
    const float* W_v   = (const float*)d_in[15];
    float* out = (float*)d_out;

    // shift the ncu capture window (-s 5 -c 1) so proj_mma_kernel gets profiled
    dummy_kernel<<<1, 32>>>(0);
    dummy_kernel<<<1, 32>>>(1);
    dummy_kernel<<<1, 32>>>(2);

    cudaFuncSetAttribute(proj_mma_kernel, cudaFuncAttributeMaxDynamicSharedMemorySize, PROJ_SMEM);
    proj_mma_kernel<<<R_ / 128, 256, PROJ_SMEM>>>(X, Wih_f, Wih_b, bih_f, bhh_f, bih_b, bhh_b);

    lstm_bi_kernel<<<dim3(64, 2), 64>>>(Whh_f, Whh_b);
    zproj_kernel<<<256, 256>>>(Wih_p, bih_p, bhh_p);
    lstm_ptr_kernel<<<128, 64>>>(Whh_p);

    const int att_smem = ATT_SMEM_FLOATS * (int)sizeof(float);  // ~37 KB
    cudaFuncSetAttribute(attn_kernel, cudaFuncAttributeMaxDynamicSharedMemorySize, att_smem);
    attn_kernel<<<128, 512, att_smem>>>(W_h, W_e, W_v, out);
}

// round 11
// speedup vs baseline: 1.2357x; 1.2357x over previous
#include <cuda_runtime.h>
#include <cuda_bf16.h>
#include <cstdint>

#define T_ 128
#define B_ 512
#define D_ 768
#define R_ (T_*B_)   // 65536 rows

typedef unsigned long long ull;

// ---------------- scratch (static device globals; no allocation) ----------------
__device__ __align__(16) float g_xproj[R_ * 64];  // [t][b][dir][u][4]
__device__ __align__(16) float g_h[R_ * 16];      // [t][b][16]: 0..7 fwd h, 8..15 bwd h
__device__ __align__(16) float g_zproj[R_ * 64];  // [t][b][u][4]
__device__ __align__(16) float g_z[R_ * 16];      // ptr-LSTM hidden states
__device__ __align__(16) __nv_bfloat16 g_eb[(size_t)T_ * B_ * B_];  // exp(S) cache, 67MB

// ---------------- helpers ----------------
__device__ __forceinline__ ull ffma2(ull a, ull b, ull c) {
    ull d;
    asm("fma.rn.f32x2 %0, %1, %2, %3;" : "=l"(d) : "l"(a), "l"(b), "l"(c));
    return d;
}
__device__ __forceinline__ ull add2(ull a, ull b) {
    ull d;
    asm("add.rn.f32x2 %0, %1, %2;" : "=l"(d) : "l"(a), "l"(b));
    return d;
}
__device__ __forceinline__ ull pack2(float lo, float hi) {
    ull r;
    asm("mov.b64 %0, {%1, %2};" : "=l"(r) : "f"(lo), "f"(hi));
    return r;
}
__device__ __forceinline__ float2 unpack2(ull v) {
    float lo, hi;
    asm("mov.b64 {%0, %1}, %2;" : "=f"(lo), "=f"(hi) : "l"(v));
    return make_float2(lo, hi);
}
__device__ __forceinline__ float tanh_hw(float x) {
    float y;
    asm("tanh.approx.f32 %0, %1;" : "=f"(y) : "f"(x));
    return y;
}
__device__ __forceinline__ float sigm_hw(float x) {
    return __fmaf_rn(0.5f, tanh_hw(0.5f * x), 0.5f);
}
__device__ __forceinline__ float ex2(float x) {
    float y;
    asm("ex2.approx.f32 %0, %1;" : "=f"(y) : "f"(x));
    return y;
}
__device__ __forceinline__ uint32_t smem_u32(const void* p) {
    uint32_t a;
    asm("{ .reg .u64 t; cvta.to.shared.u64 t, %1; cvt.u32.u64 %0, t; }" : "=r"(a) : "l"(p));
    return a;
}
__device__ __forceinline__ int bi_row_of_col(int c, int& dir) {
    dir = c >> 5;
    int w = c & 31;
    return (w & 3) * 8 + (w >> 2);
}

// ---------------- warp MMA (HMMA, plain PTX — works on bare sm_103) ----------------
__device__ __forceinline__ void mma_bf16(float* c, const uint32_t* a, uint32_t b0, uint32_t b1) {
    asm volatile(
        "mma.sync.aligned.m16n8k16.row.col.f32.bf16.bf16.f32 "
        "{%0,%1,%2,%3}, {%4,%5,%6,%7}, {%8,%9}, {%0,%1,%2,%3};"
        : "+f"(c[0]), "+f"(c[1]), "+f"(c[2]), "+f"(c[3])
        : "r"(a[0]), "r"(a[1]), "r"(a[2]), "r"(a[3]), "r"(b0), "r"(b1));
}
__device__ __forceinline__ void ldm4(uint32_t* r, uint32_t addr) {
    asm volatile("ldmatrix.sync.aligned.m8n8.x4.shared.b16 {%0,%1,%2,%3}, [%4];"
                 : "=r"(r[0]), "=r"(r[1]), "=r"(r[2]), "=r"(r[3]) : "r"(addr));
}

// ---------------- K1: HMMA projection GEMM (double-buffered pipeline) ----------------
// C[R x 64] = X[R x 768] @ Wperm^T + bias, bf16 hi/lo split (3 MMAs), fp32 accum.
// Per CTA: M=128 rows, N=64, K in 12 chunks of 64. Two 48KB smem buffers:
// chunk kc+1's LDGs are in flight while chunk kc's MMAs run.
#define PA_HI 0
#define PA_LO 16384
#define PB_HI 32768
#define PB_LO 40960
#define PBUF  49152
#define PROJ_SMEM (2 * PBUF)
#define NKC 12

__device__ __forceinline__ void cvt_hilo8(float4 v0, float4 v1, uint4& hi, uint4& lo) {
    float xs[8] = {v0.x, v0.y, v0.z, v0.w, v1.x, v1.y, v1.z, v1.w};
    uint32_t h[4], l[4];
    #pragma unroll
    for (int i = 0; i < 4; i++) {
        float a = xs[2 * i], b = xs[2 * i + 1];
        uint32_t hp;
        asm("cvt.rn.bf16x2.f32 %0, %1, %2;" : "=r"(hp) : "f"(b), "f"(a));
        float fa = __uint_as_float(hp << 16);
        float fb = __uint_as_float(hp & 0xffff0000u);
        float la = a - fa, lb = b - fb;
        uint32_t lp;
        asm("cvt.rn.bf16x2.f32 %0, %1, %2;" : "=r"(lp) : "f"(lb), "f"(la));
        h[i] = hp; l[i] = lp;
    }
    hi = make_uint4(h[0], h[1], h[2], h[3]);
    lo = make_uint4(l[0], l[1], l[2], l[3]);
}

__global__ void __launch_bounds__(256, 2) proj_mma_kernel(
    const float* __restrict__ X,
    const float* __restrict__ Wf, const float* __restrict__ Wb,
    const float* __restrict__ bif, const float* __restrict__ bhf,
    const float* __restrict__ bib, const float* __restrict__ bhb)
{
    extern __shared__ __align__(1024) char psm[];
    __shared__ float bias[64];
    const uint32_t smem_base = smem_u32(psm);
    const int tid = threadIdx.x;
    const int w = tid >> 5, lane = tid & 31;
    const int row0 = blockIdx.x * 128;

    if (tid < 64) {
        int dir;
        int r = bi_row_of_col(tid, dir);
        bias[tid] = dir ? (bib[r] + bhb[r]) : (bif[r] + bhf[r]);
    }

    const int rowA = 16 * w + (lane & 15);
    const uint32_t aRow = smem_base + rowA * 128;
    const uint32_t axr = (rowA & 7) << 4;
    const uint32_t akoff = (lane >= 16) ? 16u : 0u;

    const int nB = (lane & 7) + ((lane >> 4) << 3);
    const uint32_t bxr = (lane & 7) << 4;
    const uint32_t bkoff = (lane & 8) ? 16u : 0u;

    float acc[32];
    #pragma unroll
    for (int i = 0; i < 32; i++) acc[i] = 0.f;

    float4 areg[8], breg[4];

    auto load_regs = [&](int kc) {
        const int k0 = kc * 64;
        #pragma unroll
        for (int q = 0; q < 4; q++) {
            int unit = tid + q * 256;
            int r = unit >> 3, c8 = unit & 7;
            const float* p = X + (size_t)(row0 + r) * D_ + k0 + c8 * 8;
            areg[2 * q]     = *(const float4*)p;
            areg[2 * q + 1] = *(const float4*)(p + 4);
        }
        #pragma unroll
        for (int q = 0; q < 2; q++) {
            int unit = tid + q * 256;
            int n = unit >> 3, c8 = unit & 7;
            int dir;
            int rr = bi_row_of_col(n, dir);
            const float* p = (dir ? Wb : Wf) + rr * D_ + k0 + c8 * 8;
            breg[2 * q]     = *(const float4*)p;
            breg[2 * q + 1] = *(const float4*)(p + 4);
        }
    };

    auto cvt_store = [&](int bufidx) {
        char* base = psm + bufidx * PBUF;
        #pragma unroll
        for (int q = 0; q < 4; q++) {
            int unit = tid + q * 256;
            int r = unit >> 3, c8 = unit & 7;
            uint32_t off = r * 128 + c8 * 16;
            uint32_t sw = off ^ ((off >> 3) & 0x70);
            uint4 hi, lo;
            cvt_hilo8(areg[2 * q], areg[2 * q + 1], hi, lo);
            *(uint4*)(base + PA_HI + sw) = hi;
            *(uint4*)(base + PA_LO + sw) = lo;
        }
        #pragma unroll
        for (int q = 0; q < 2; q++) {
            int unit = tid + q * 256;
            int n = unit >> 3, c8 = unit & 7;
            uint32_t off = n * 128 + c8 * 16;
            uint32_t sw = off ^ ((off >> 3) & 0x70);
            uint4 hi, lo;
            cvt_hilo8(breg[2 * q], breg[2 * q + 1], hi, lo);
            *(uint4*)(base + PB_HI + sw) = hi;
            *(uint4*)(base + PB_LO + sw) = lo;
        }
    };

    auto mma_phase = [&](uint32_t bofs) {
        #pragma unroll
        for (int ks = 0; ks < 4; ks++) {
            const uint32_t ak = (ks * 32 + akoff) ^ axr;
            uint32_t ahi[4], alo[4];
            ldm4(ahi, aRow + bofs + PA_HI + ak);
            ldm4(alo, aRow + bofs + PA_LO + ak);
            #pragma unroll
            for (int np = 0; np < 4; np++) {
                const int n = np * 16 + nB;
                const uint32_t bk = (uint32_t)n * 128 + ((ks * 32 + bkoff) ^ bxr);
                uint32_t bhi[4], blo[4];
                ldm4(bhi, smem_base + bofs + PB_HI + bk);
                ldm4(blo, smem_base + bofs + PB_LO + bk);
                float* c0 = acc + (2 * np) * 4;
                float* c1 = acc + (2 * np + 1) * 4;
                mma_bf16(c0, ahi, bhi[0], bhi[1]);
                mma_bf16(c0, ahi, blo[0], blo[1]);
                mma_bf16(c0, alo, bhi[0], bhi[1]);
                mma_bf16(c1, ahi, bhi[2], bhi[3]);
                mma_bf16(c1, ahi, blo[2], blo[3]);
                mma_bf16(c1, alo, bhi[2], bhi[3]);
            }
        }
    };

    // prologue: chunk 0 into buffer 0
    load_regs(0);
    cvt_store(0);
    __syncthreads();

    for (int kc = 0; kc < NKC; kc++) {
        if (kc + 1 < NKC) load_regs(kc + 1);      // LDGs in flight during MMA
        mma_phase((uint32_t)(kc & 1) * PBUF);
        if (kc + 1 < NKC) {
            cvt_store((kc + 1) & 1);
            __syncthreads();
        }
    }

    const int g = lane >> 2, tq = (lane & 3) * 2;
    const int r0 = row0 + 16 * w + g;
    #pragma unroll
    for (int nt = 0; nt < 8; nt++) {
        int col = nt * 8 + tq;
        float b0 = bias[col], b1 = bias[col + 1];
        float* d0 = g_xproj + (size_t)r0 * 64 + col;
        float* d1 = g_xproj + (size_t)(r0 + 8) * 64 + col;
        *(float2*)d0 = make_float2(acc[nt * 4 + 0] + b0, acc[nt * 4 + 1] + b1);
        *(float2*)d1 = make_float2(acc[nt * 4 + 2] + b0, acc[nt * 4 + 3] + b1);
    }
}

// ---------------- scan dot helpers (packed h in registers) ----------------
__device__ __forceinline__ float dot8p(ull h01, ull h23, ull h45, ull h67,
                                       ulonglong2 w01, ulonglong2 w23, float x) {
    ull a0 = ffma2(h45, w23.x, ffma2(h01, w01.x, 0ULL));
    ull a1 = ffma2(h67, w23.y, ffma2(h23, w01.y, 0ULL));
    float2 v = unpack2(add2(a0, a1));
    return x + v.x + v.y;
}
__device__ __forceinline__ float dot16p(const ull* hp, const ulonglong2* w, float x) {
    ull a0 = ffma2(hp[4], w[2].x, ffma2(hp[0], w[0].x, 0ULL));
    ull a1 = ffma2(hp[5], w[2].y, ffma2(hp[1], w[0].y, 0ULL));
    ull a2 = ffma2(hp[6], w[3].x, ffma2(hp[2], w[1].x, 0ULL));
    ull a3 = ffma2(hp[7], w[3].y, ffma2(hp[3], w[1].y, 0ULL));
    float2 v = unpack2(add2(add2(a0, a1), add2(a2, a3)));
    return x + v.x + v.y;
}

// ---------------- K2: bidirectional LSTM scan (H=8) ----------------
__global__ void __launch_bounds__(64) lstm_bi_kernel(
    const float* __restrict__ Whhf, const float* __restrict__ Whhb)
{
    const int tid = threadIdx.x;
    const int dir = blockIdx.y;
    const int e = tid >> 3, u = tid & 7;
    const int b = blockIdx.x * 8 + e;
    const int base = tid & 24;

    const float* W = dir ? Whhb : Whhf;
    ulonglong2 wi0 = *(const ulonglong2*)(W + u * 8);
    ulonglong2 wi1 = *(const ulonglong2*)(W + u * 8 + 4);
    ulonglong2 wf0 = *(const ulonglong2*)(W + (8 + u) * 8);
    ulonglong2 wf1 = *(const ulonglong2*)(W + (8 + u) * 8 + 4);
    ulonglong2 wg0 = *(const ulonglong2*)(W + (16 + u) * 8);
    ulonglong2 wg1 = *(const ulonglong2*)(W + (16 + u) * 8 + 4);
    ulonglong2 wo0 = *(const ulonglong2*)(W + (24 + u) * 8);
    ulonglong2 wo1 = *(const ulonglong2*)(W + (24 + u) * 8 + 4);

    float hv[8];
    #pragma unroll
    for (int j = 0; j < 8; j++) hv[j] = 0.f;
    float cu = 0.f;

    const float4* xsrc = (const float4*)g_xproj;
    const long long stride4 = (long long)B_ * 16;
    const long long step = dir ? -stride4 : stride4;
    long long idx = ((long long)(dir ? T_ - 1 : 0) * B_ + b) * 16 + dir * 8 + u;
    float4 buf[4];
    #pragma unroll
    for (int p = 0; p < 4; p++) buf[p] = xsrc[idx + p * step];

    float* hp0 = g_h + (size_t)b * 16 + dir * 8 + u;

    #pragma unroll 4
    for (int s = 0; s < T_; s++) {
        const int tt = dir ? (T_ - 1 - s) : s;
        float4 x = buf[s & 3];
        if (s + 4 < T_) buf[s & 3] = xsrc[idx + (long long)(s + 4) * step];

        ull h01 = pack2(hv[0], hv[1]), h23 = pack2(hv[2], hv[3]);
        ull h45 = pack2(hv[4], hv[5]), h67 = pack2(hv[6], hv[7]);

        float gi = dot8p(h01, h23, h45, h67, wi0, wi1, x.x);
        float gf = dot8p(h01, h23, h45, h67, wf0, wf1, x.y);
        float gg = dot8p(h01, h23, h45, h67, wg0, wg1, x.z);
        float go = dot8p(h01, h23, h45, h67, wo0, wo1, x.w);

        float ii = sigm_hw(gi), ff = sigm_hw(gf);
        float g2 = tanh_hw(gg), oo = sigm_hw(go);
        cu = __fmaf_rn(ff, cu, ii * g2);
        float hu = oo * tanh_hw(cu);
        #pragma unroll
        for (int j = 0; j < 8; j++)
            hv[j] = __shfl_sync(0xffffffffu, hu, base + j);
        hp0[(size_t)tt * (B_ * 16)] = hu;
    }
}

// ---------------- K3: ptr-LSTM input projection (gate-interleaved output) -------
__global__ void __launch_bounds__(256) zproj_kernel(
    const float* __restrict__ Wihp, const float* __restrict__ bip,
    const float* __restrict__ bhp)
{
    __shared__ float W[64][16];
    __shared__ float bias[64];
    const int tid = threadIdx.x;
    #pragma unroll
    for (int i = tid; i < 1024; i += 256) {
        int n = i >> 4, k = i & 15;
        int u = n >> 2, g = n & 3;
        W[n][k] = Wihp[(g * 16 + u) * 16 + k];
    }
    if (tid < 64) {
        int u = tid >> 2, g = tid & 3;
        int r = g * 16 + u;
        bias[tid] = bip[r] + bhp[r];
    }
    __syncthreads();

    size_t r = (size_t)blockIdx.x * 256 + tid;
    const float4* h4 = (const float4*)(g_h + r * 16);
    float4 a0 = h4[0], a1 = h4[1], a2 = h4[2], a3 = h4[3];
    float hr[16] = {a0.x, a0.y, a0.z, a0.w, a1.x, a1.y, a1.z, a1.w,
                    a2.x, a2.y, a2.z, a2.w, a3.x, a3.y, a3.z, a3.w};
    float* out = g_zproj + r * 64;
    #pragma unroll
    for (int g0 = 0; g0 < 64; g0 += 4) {
        float o[4];
        #pragma unroll
        for (int q = 0; q < 4; q++) {
            int g = g0 + q;
            float a = bias[g];
            #pragma unroll
            for (int k = 0; k < 16; k++) a = __fmaf_rn(W[g][k], hr[k], a);
            o[q] = a;
        }
        *(float4*)(out + g0) = make_float4(o[0], o[1], o[2], o[3]);
    }
}

// ---------------- K4: ptr LSTM scan (H=16) ----------------
__global__ void __launch_bounds__(64) lstm_ptr_kernel(const float* __restrict__ Whhp)
{
    const int tid = threadIdx.x;
    const int e = tid >> 4, u = tid & 15;
    const int b = blockIdx.x * 4 + e;
    const int base = tid & 16;

    ulonglong2 wi[4], wf4[4], wg4[4], wo4[4];
    {
        const ulonglong2* p;
        p = (const ulonglong2*)(Whhp + u * 16);
        wi[0] = p[0]; wi[1] = p[1]; wi[2] = p[2]; wi[3] = p[3];
        p = (const ulonglong2*)(Whhp + (16 + u) * 16);
        wf4[0] = p[0]; wf4[1] = p[1]; wf4[2] = p[2]; wf4[3] = p[3];
        p = (const ulonglong2*)(Whhp + (32 + u) * 16);
        wg4[0] = p[0]; wg4[1] = p[1]; wg4[2] = p[2]; wg4[3] = p[3];
        p = (const ulonglong2*)(Whhp + (48 + u) * 16);
        wo4[0] = p[0]; wo4[1] = p[1]; wo4[2] = p[2]; wo4[3] = p[3];
    }

    float hv[16];
    #pragma unroll
    for (int j = 0; j < 16; j++) hv[j] = 0.f;
    float cu = 0.f;

    const float4* zsrc = (const float4*)g_zproj;
    const long long stride4 = (long long)B_ * 16;
    long long idx = (long long)b * 16 + u;
    float4 buf[4];
    #pragma unroll
    for (int p = 0; p < 4; p++) buf[p] = zsrc[idx + p * stride4];

    float* zp0 = g_z + (size_t)b * 16 + u;

    #pragma unroll 4
    for (int t = 0; t < T_; t++) {
        float4 x = buf[t & 3];
        if (t + 4 < T_) buf[t & 3] = zsrc[idx + (long long)(t + 4) * stride4];

        ull hp[8];
        #pragma unroll
        for (int j = 0; j < 8; j++) hp[j] = pack2(hv[2 * j], hv[2 * j + 1]);

        float gi = dot16p(hp, wi,  x.x);
        float gf = dot16p(hp, wf4, x.y);
        float gg = dot16p(hp, wg4, x.z);
        float go = dot16p(hp, wo4, x.w);

        float ii = sigm_hw(gi), ff = sigm_hw(gf);
        float g2 = tanh_hw(gg), oo = sigm_hw(go);
        cu = __fmaf_rn(ff, cu, ii * g2);
        float hu = oo * tanh_hw(cu);
        #pragma unroll
        for (int j = 0; j < 16; j++)
            hv[j] = __shfl_sync(0xffffffffu, hu, base + j);
        zp0[(size_t)t * (B_ * 16)] = hu;
    }
}

// ---------------- K5: fused attention + output head, one CTA per t ----------------
#define ATT_SMEM_FLOATS (8192 + 512 + 256 + 256 + 16)
__global__ void __launch_bounds__(512) attn_kernel(
    const float* __restrict__ W_h, const float* __restrict__ W_e,
    const float* __restrict__ W_v, float* __restrict__ out)
{
    extern __shared__ __align__(16) float sm[];
    float* hs   = sm;            // 512 x 16
    float* cinv = sm + 8192;     // 512
    float* whs  = sm + 8704;     // 16 x 16
    float* wes  = sm + 8960;     // 16 x 16
    float* wvs  = sm + 9216;     // 16

    const int tid = threadIdx.x;
    const int t = blockIdx.x;
    {
        const float4* hsrc = (const float4*)(g_h + (size_t)t * (B_ * 16));
        float4* hd = (float4*)hs;
        #pragma unroll
        for (int i = 0; i < 4; i++) hd[tid + i * 512] = hsrc[tid + i * 512];
    }
    if (tid < 256) { whs[tid] = W_h[tid]; wes[tid] = W_e[tid]; }
    if (tid < 16)  wvs[tid] = W_v[tid];
    __syncthreads();

    // ---- pass 1: thread c owns column c -> exp store + colsum ----
    {
        const float L2E = 1.44269504f;
        const float4* zg = (const float4*)(g_z + (size_t)t * (B_ * 16) + (size_t)tid * 16);
        float4 z0 = zg[0], z1 = zg[1], z2 = zg[2], z3 = zg[3];
        ull zq[8];
        zq[0] = pack2(z0.x * L2E, z0.y * L2E); zq[1] = pack2(z0.z * L2E, z0.w * L2E);
        zq[2] = pack2(z1.x * L2E, z1.y * L2E); zq[3] = pack2(z1.z * L2E, z1.w * L2E);
        zq[4] = pack2(z2.x * L2E, z2.y * L2E); zq[5] = pack2(z2.z * L2E, z2.w * L2E);
        zq[6] = pack2(z3.x * L2E, z3.y * L2E); zq[7] = pack2(z3.z * L2E, z3.w * L2E);

        __nv_bfloat16* ecol = g_eb + (size_t)t * B_ * B_ + tid;
        float colsum = 0.f;
        #pragma unroll 2
        for (int bb = 0; bb < B_; bb++) {
            const ulonglong2* hr = (const ulonglong2*)(hs + bb * 16);
            ulonglong2 hq0 = hr[0], hq1 = hr[1], hq2 = hr[2], hq3 = hr[3];
            ull aA = 0ULL, aB = 0ULL;
            aA = ffma2(hq0.x, zq[0], aA); aB = ffma2(hq0.y, zq[1], aB);
            aA = ffma2(hq1.x, zq[2], aA); aB = ffma2(hq1.y, zq[3], aB);
            aA = ffma2(hq2.x, zq[4], aA); aB = ffma2(hq2.y, zq[5], aB);
            aA = ffma2(hq3.x, zq[6], aA); aB = ffma2(hq3.y, zq[7], aB);
            float2 va = unpack2(aA), vb = unpack2(aB);
            float S = (va.x + va.y) + (vb.x + vb.y);
            float e = ex2(S);
            __nv_bfloat16 eb = __float2bfloat16(e);
            ecol[(size_t)bb * B_] = eb;
            colsum += __bfloat162float(eb);
        }
        cinv[tid] = __fdividef(1.f, colsum);
    }
    __syncthreads();

    // ---- pass 2 + output head: thread b owns row b ----
    {
        ull cacc[8];
        #pragma unroll
        for (int k = 0; k < 8; k++) cacc[k] = 0ULL;

        const __nv_bfloat16* erow = g_eb + (size_t)t * B_ * B_ + (size_t)tid * B_;
        for (int c0 = 0; c0 < B_; c0 += 8) {
            uint4 ev = *(const uint4*)(erow + c0);
            float4 ci0 = *(const float4*)(cinv + c0);
            float4 ci1 = *(const float4*)(cinv + c0 + 4);
            uint32_t uu[4] = {ev.x, ev.y, ev.z, ev.w};
            float cis[8] = {ci0.x, ci0.y, ci0.z, ci0.w, ci1.x, ci1.y, ci1.z, ci1.w};
            #pragma unroll
            for (int k = 0; k < 4; k++) {
                float e0 = __uint_as_float(uu[k] << 16);
                float e1 = __uint_as_float(uu[k] & 0xffff0000u);
                float w0 = e0 * cis[2 * k];
                float w1 = e1 * cis[2 * k + 1];
                {
                    ull w2 = pack2(w0, w0);
                    const ulonglong2* hc = (const ulonglong2*)(hs + (c0 + 2 * k) * 16);
                    ulonglong2 q0 = hc[0], q1 = hc[1], q2 = hc[2], q3 = hc[3];
                    cacc[0] = ffma2(q0.x, w2, cacc[0]); cacc[1] = ffma2(q0.y, w2, cacc[1]);
                    cacc[2] = ffma2(q1.x, w2, cacc[2]); cacc[3] = ffma2(q1.y, w2, cacc[3]);
                    cacc[4] = ffma2(q2.x, w2, cacc[4]); cacc[5] = ffma2(q2.y, w2, cacc[5]);
                    cacc[6] = ffma2(q3.x, w2, cacc[6]); cacc[7] = ffma2(q3.y, w2, cacc[7]);
                }
                {
                    ull w2 = pack2(w1, w1);
                    const ulonglong2* hc = (const ulonglong2*)(hs + (c0 + 2 * k + 1) * 16);
                    ulonglong2 q0 = hc[0], q1 = hc[1], q2 = hc[2], q3 = hc[3];
                    cacc[0] = ffma2(q0.x, w2, cacc[0]); cacc[1] = ffma2(q0.y, w2, cacc[1]);
                    cacc[2] = ffma2(q1.x, w2, cacc[2]); cacc[3] = ffma2(q1.y, w2, cacc[3]);
                    cacc[4] = ffma2(q2.x, w2, cacc[4]); cacc[5] = ffma2(q2.y, w2, cacc[5]);
                    cacc[6] = ffma2(q3.x, w2, cacc[6]); cacc[7] = ffma2(q3.y, w2, cacc[7]);
                }
            }
        }

        float ctxv[16], hbv[16];
        #pragma unroll
        for (int k = 0; k < 8; k++) {
            float2 v = unpack2(cacc[k]);
            ctxv[2 * k] = v.x; ctxv[2 * k + 1] = v.y;
        }
        {
            const float4* hb4 = (const float4*)(hs + tid * 16);
            float4 a0 = hb4[0], a1 = hb4[1], a2 = hb4[2], a3 = hb4[3];
            hbv[0] = a0.x;  hbv[1] = a0.y;  hbv[2] = a0.z;  hbv[3] = a0.w;
            hbv[4] = a1.x;  hbv[5] = a1.y;  hbv[6] = a1.z;  hbv[7] = a1.w;
            hbv[8] = a2.x;  hbv[9] = a2.y;  hbv[10] = a2.z; hbv[11] = a2.w;
            hbv[12] = a3.x; hbv[13] = a3.y; hbv[14] = a3.z; hbv[15] = a3.w;
        }
        float pacc = 0.f;
        #pragma unroll
        for (int d = 0; d < 16; d++) {
            float a = 0.f;
            #pragma unroll
            for (int k = 0; k < 16; k++) a = __fmaf_rn(whs[d * 16 + k], hbv[k], a);
            #pragma unroll
            for (int k = 0; k < 16; k++) a = __fmaf_rn(wes[d * 16 + k], ctxv[k], a);
            float ud = tanh_hw(a);
            pacc = __fmaf_rn(ud, wvs[d], pacc);
        }
        out[(size_t)t * B_ + tid] = sigm_hw(pacc);
    }
}

// ---------------- launch ----------------
extern "C" void kernel_launch(void* const* d_in, const int* in_sizes, int n_in,
                              void* d_out, int out_size)
{
    (void)in_sizes; (void)n_in; (void)out_size;
    const float* X     = (const float*)d_in[0];
    const float* Wih_f = (const float*)d_in[1];
    const float* Whh_f = (const float*)d_in[2];
    const float* bih_f = (const float*)d_in[3];
    const float* bhh_f = (const float*)d_in[4];
    const float* Wih_b = (const float*)d_in[5];
    const float* Whh_b = (const float*)d_in[6];
    const float* bih_b = (const float*)d_in[7];
    const float* bhh_b = (const float*)d_in[8];
    const float* Wih_p = (const float*)d_in[9];
    const float* Whh_p = (const float*)d_in[10];
    const float* bih_p = (const float*)d_in[11];
    const float* bhh_p = (const float*)d_in[12];
    const float* W_h   = (const float*)d_in[13];
    const float* W_e   = (const float*)d_in[14];
    const float* W_v   = (const float*)d_in[15];
    float* out = (float*)d_out;

    cudaFuncSetAttribute(proj_mma_kernel, cudaFuncAttributeMaxDynamicSharedMemorySize, PROJ_SMEM);
    proj_mma_kernel<<<R_ / 128, 256, PROJ_SMEM>>>(X, Wih_f, Wih_b, bih_f, bhh_f, bih_b, bhh_b);

    lstm_bi_kernel<<<dim3(64, 2), 64>>>(Whh_f, Whh_b);
    zproj_kernel<<<256, 256>>>(Wih_p, bih_p, bhh_p);
    lstm_ptr_kernel<<<128, 64>>>(Whh_p);

    const int att_smem = ATT_SMEM_FLOATS * (int)sizeof(float);  // ~37 KB
    cudaFuncSetAttribute(attn_kernel, cudaFuncAttributeMaxDynamicSharedMemorySize, att_smem);
    attn_kernel<<<128, 512, att_smem>>>(W_h, W_e, W_v, out);
}

// round 12
// speedup vs baseline: 1.6930x; 1.3701x over previous
#include <cuda_runtime.h>
#include <cuda_bf16.h>
#include <cstdint>

#define T_ 128
#define B_ 512
#define D_ 768
#define R_ (T_*B_)   // 65536 rows

typedef unsigned long long ull;

// ---------------- scratch (static device globals; no allocation) ----------------
__device__ __align__(16) float g_xproj[R_ * 64];  // [t][b][dir][u][4]
__device__ __align__(16) float g_h[R_ * 16];      // [t][b][16]
__device__ __align__(16) float g_zproj[R_ * 64];  // [t][b][u][4]
__device__ __align__(16) float g_z[R_ * 16];      // ptr-LSTM hidden states

// ---------------- helpers ----------------
__device__ __forceinline__ ull ffma2(ull a, ull b, ull c) {
    ull d;
    asm("fma.rn.f32x2 %0, %1, %2, %3;" : "=l"(d) : "l"(a), "l"(b), "l"(c));
    return d;
}
__device__ __forceinline__ ull add2(ull a, ull b) {
    ull d;
    asm("add.rn.f32x2 %0, %1, %2;" : "=l"(d) : "l"(a), "l"(b));
    return d;
}
__device__ __forceinline__ ull pack2(float lo, float hi) {
    ull r;
    asm("mov.b64 %0, {%1, %2};" : "=l"(r) : "f"(lo), "f"(hi));
    return r;
}
__device__ __forceinline__ float2 unpack2(ull v) {
    float lo, hi;
    asm("mov.b64 {%0, %1}, %2;" : "=f"(lo), "=f"(hi) : "l"(v));
    return make_float2(lo, hi);
}
__device__ __forceinline__ float tanh_hw(float x) {
    float y;
    asm("tanh.approx.f32 %0, %1;" : "=f"(y) : "f"(x));
    return y;
}
__device__ __forceinline__ float sigm_hw(float x) {
    return __fmaf_rn(0.5f, tanh_hw(0.5f * x), 0.5f);
}
__device__ __forceinline__ float ex2(float x) {
    float y;
    asm("ex2.approx.f32 %0, %1;" : "=f"(y) : "f"(x));
    return y;
}
__device__ __forceinline__ uint32_t cvt2(float hi, float lo) {
    uint32_t r;
    asm("cvt.rn.bf16x2.f32 %0, %1, %2;" : "=r"(r) : "f"(hi), "f"(lo));
    return r;
}
__device__ __forceinline__ float flo(uint32_t r) { return __uint_as_float(r << 16); }
__device__ __forceinline__ float fhi(uint32_t r) { return __uint_as_float(r & 0xffff0000u); }
__device__ __forceinline__ uint32_t smem_u32(const void* p) {
    uint32_t a;
    asm("{ .reg .u64 t; cvta.to.shared.u64 t, %1; cvt.u32.u64 %0, t; }" : "=r"(a) : "l"(p));
    return a;
}
__device__ __forceinline__ int bi_row_of_col(int c, int& dir) {
    dir = c >> 5;
    int w = c & 31;
    return (w & 3) * 8 + (w >> 2);
}

// ---------------- warp MMA (HMMA, plain PTX — works on bare sm_103) ----------------
__device__ __forceinline__ void mma_bf16(float* c, const uint32_t* a, uint32_t b0, uint32_t b1) {
    asm volatile(
        "mma.sync.aligned.m16n8k16.row.col.f32.bf16.bf16.f32 "
        "{%0,%1,%2,%3}, {%4,%5,%6,%7}, {%8,%9}, {%0,%1,%2,%3};"
        : "+f"(c[0]), "+f"(c[1]), "+f"(c[2]), "+f"(c[3])
        : "r"(a[0]), "r"(a[1]), "r"(a[2]), "r"(a[3]), "r"(b0), "r"(b1));
}
__device__ __forceinline__ void ldm4(uint32_t* r, uint32_t addr) {
    asm volatile("ldmatrix.sync.aligned.m8n8.x4.shared.b16 {%0,%1,%2,%3}, [%4];"
                 : "=r"(r[0]), "=r"(r[1]), "=r"(r[2]), "=r"(r[3]) : "r"(addr));
}
__device__ __forceinline__ void ldm2(uint32_t* r, uint32_t addr) {
    asm volatile("ldmatrix.sync.aligned.m8n8.x2.shared.b16 {%0,%1}, [%2];"
                 : "=r"(r[0]), "=r"(r[1]) : "r"(addr));
}

__device__ __forceinline__ void cvt_hilo8(float4 v0, float4 v1, uint4& hi, uint4& lo) {
    float xs[8] = {v0.x, v0.y, v0.z, v0.w, v1.x, v1.y, v1.z, v1.w};
    uint32_t h[4], l[4];
    #pragma unroll
    for (int i = 0; i < 4; i++) {
        float a = xs[2 * i], b = xs[2 * i + 1];
        uint32_t hp = cvt2(b, a);   // lo16=a, hi16=b
        float fa = flo(hp), fb = fhi(hp);
        uint32_t lp = cvt2(b - fb, a - fa);
        h[i] = hp; l[i] = lp;
    }
    hi = make_uint4(h[0], h[1], h[2], h[3]);
    lo = make_uint4(l[0], l[1], l[2], l[3]);
}

// ---------------- K1: HMMA projection GEMM (double-buffered pipeline) ----------------
#define PA_HI 0
#define PA_LO 16384
#define PB_HI 32768
#define PB_LO 40960
#define PBUF  49152
#define PROJ_SMEM (2 * PBUF)
#define NKC 12

__global__ void __launch_bounds__(256, 2) proj_mma_kernel(
    const float* __restrict__ X,
    const float* __restrict__ Wf, const float* __restrict__ Wb,
    const float* __restrict__ bif, const float* __restrict__ bhf,
    const float* __restrict__ bib, const float* __restrict__ bhb)
{
    extern __shared__ __align__(1024) char psm[];
    __shared__ float bias[64];
    const uint32_t smem_base = smem_u32(psm);
    const int tid = threadIdx.x;
    const int w = tid >> 5, lane = tid & 31;
    const int row0 = blockIdx.x * 128;

    if (tid < 64) {
        int dir;
        int r = bi_row_of_col(tid, dir);
        bias[tid] = dir ? (bib[r] + bhb[r]) : (bif[r] + bhf[r]);
    }

    const int rowA = 16 * w + (lane & 15);
    const uint32_t aRow = smem_base + rowA * 128;
    const uint32_t axr = (rowA & 7) << 4;
    const uint32_t akoff = (lane >= 16) ? 16u : 0u;

    const int nB = (lane & 7) + ((lane >> 4) << 3);
    const uint32_t bxr = (lane & 7) << 4;
    const uint32_t bkoff = (lane & 8) ? 16u : 0u;

    float acc[32];
    #pragma unroll
    for (int i = 0; i < 32; i++) acc[i] = 0.f;

    float4 areg[8], breg[4];

    auto load_regs = [&](int kc) {
        const int k0 = kc * 64;
        #pragma unroll
        for (int q = 0; q < 4; q++) {
            int unit = tid + q * 256;
            int r = unit >> 3, c8 = unit & 7;
            const float* p = X + (size_t)(row0 + r) * D_ + k0 + c8 * 8;
            areg[2 * q]     = *(const float4*)p;
            areg[2 * q + 1] = *(const float4*)(p + 4);
        }
        #pragma unroll
        for (int q = 0; q < 2; q++) {
            int unit = tid + q * 256;
            int n = unit >> 3, c8 = unit & 7;
            int dir;
            int rr = bi_row_of_col(n, dir);
            const float* p = (dir ? Wb : Wf) + rr * D_ + k0 + c8 * 8;
            breg[2 * q]     = *(const float4*)p;
            breg[2 * q + 1] = *(const float4*)(p + 4);
        }
    };

    auto cvt_store = [&](int bufidx) {
        char* base = psm + bufidx * PBUF;
        #pragma unroll
        for (int q = 0; q < 4; q++) {
            int unit = tid + q * 256;
            int r = unit >> 3, c8 = unit & 7;
            uint32_t off = r * 128 + c8 * 16;
            uint32_t sw = off ^ ((off >> 3) & 0x70);
            uint4 hi, lo;
            cvt_hilo8(areg[2 * q], areg[2 * q + 1], hi, lo);
            *(uint4*)(base + PA_HI + sw) = hi;
            *(uint4*)(base + PA_LO + sw) = lo;
        }
        #pragma unroll
        for (int q = 0; q < 2; q++) {
            int unit = tid + q * 256;
            int n = unit >> 3, c8 = unit & 7;
            uint32_t off = n * 128 + c8 * 16;
            uint32_t sw = off ^ ((off >> 3) & 0x70);
            uint4 hi, lo;
            cvt_hilo8(breg[2 * q], breg[2 * q + 1], hi, lo);
            *(uint4*)(base + PB_HI + sw) = hi;
            *(uint4*)(base + PB_LO + sw) = lo;
        }
    };

    auto mma_phase = [&](uint32_t bofs) {
        #pragma unroll
        for (int ks = 0; ks < 4; ks++) {
            const uint32_t ak = (ks * 32 + akoff) ^ axr;
            uint32_t ahi[4], alo[4];
            ldm4(ahi, aRow + bofs + PA_HI + ak);
            ldm4(alo, aRow + bofs + PA_LO + ak);
            #pragma unroll
            for (int np = 0; np < 4; np++) {
                const int n = np * 16 + nB;
                const uint32_t bk = (uint32_t)n * 128 + ((ks * 32 + bkoff) ^ bxr);
                uint32_t bhi[4], blo[4];
                ldm2(bhi, smem_base + bofs + PB_HI + bk);
                ldm2(bhi + 2, smem_base + bofs + PB_HI + bk + 0);  // placeholder overwritten below
                ldm4(bhi, smem_base + bofs + PB_HI + bk);
                ldm4(blo, smem_base + bofs + PB_LO + bk);
                float* c0 = acc + (2 * np) * 4;
                float* c1 = acc + (2 * np + 1) * 4;
                mma_bf16(c0, ahi, bhi[0], bhi[1]);
                mma_bf16(c0, ahi, blo[0], blo[1]);
                mma_bf16(c0, alo, bhi[0], bhi[1]);
                mma_bf16(c1, ahi, bhi[2], bhi[3]);
                mma_bf16(c1, ahi, blo[2], blo[3]);
                mma_bf16(c1, alo, bhi[2], bhi[3]);
            }
        }
    };

    load_regs(0);
    cvt_store(0);
    __syncthreads();

    for (int kc = 0; kc < NKC; kc++) {
        if (kc + 1 < NKC) load_regs(kc + 1);
        mma_phase((uint32_t)(kc & 1) * PBUF);
        if (kc + 1 < NKC) {
            cvt_store((kc + 1) & 1);
            __syncthreads();
        }
    }

    const int g = lane >> 2, tq = (lane & 3) * 2;
    const int r0 = row0 + 16 * w + g;
    #pragma unroll
    for (int nt = 0; nt < 8; nt++) {
        int col = nt * 8 + tq;
        float b0 = bias[col], b1 = bias[col + 1];
        float* d0 = g_xproj + (size_t)r0 * 64 + col;
        float* d1 = g_xproj + (size_t)(r0 + 8) * 64 + col;
        *(float2*)d0 = make_float2(acc[nt * 4 + 0] + b0, acc[nt * 4 + 1] + b1);
        *(float2*)d1 = make_float2(acc[nt * 4 + 2] + b0, acc[nt * 4 + 3] + b1);
    }
}

// ---------------- scan dot helpers (packed h in registers) ----------------
__device__ __forceinline__ float dot8p(ull h01, ull h23, ull h45, ull h67,
                                       ulonglong2 w01, ulonglong2 w23, float x) {
    ull a0 = ffma2(h45, w23.x, ffma2(h01, w01.x, 0ULL));
    ull a1 = ffma2(h67, w23.y, ffma2(h23, w01.y, 0ULL));
    float2 v = unpack2(add2(a0, a1));
    return x + v.x + v.y;
}
__device__ __forceinline__ float dot16p(const ull* hp, const ulonglong2* w, float x) {
    ull a0 = ffma2(hp[4], w[2].x, ffma2(hp[0], w[0].x, 0ULL));
    ull a1 = ffma2(hp[5], w[2].y, ffma2(hp[1], w[0].y, 0ULL));
    ull a2 = ffma2(hp[6], w[3].x, ffma2(hp[2], w[1].x, 0ULL));
    ull a3 = ffma2(hp[7], w[3].y, ffma2(hp[3], w[1].y, 0ULL));
    float2 v = unpack2(add2(add2(a0, a1), add2(a2, a3)));
    return x + v.x + v.y;
}

// ---------------- K2: bidirectional LSTM scan (H=8) ----------------
__global__ void __launch_bounds__(64) lstm_bi_kernel(
    const float* __restrict__ Whhf, const float* __restrict__ Whhb)
{
    const int tid = threadIdx.x;
    const int dir = blockIdx.y;
    const int e = tid >> 3, u = tid & 7;
    const int b = blockIdx.x * 8 + e;
    const int base = tid & 24;

    const float* W = dir ? Whhb : Whhf;
    ulonglong2 wi0 = *(const ulonglong2*)(W + u * 8);
    ulonglong2 wi1 = *(const ulonglong2*)(W + u * 8 + 4);
    ulonglong2 wf0 = *(const ulonglong2*)(W + (8 + u) * 8);
    ulonglong2 wf1 = *(const ulonglong2*)(W + (8 + u) * 8 + 4);
    ulonglong2 wg0 = *(const ulonglong2*)(W + (16 + u) * 8);
    ulonglong2 wg1 = *(const ulonglong2*)(W + (16 + u) * 8 + 4);
    ulonglong2 wo0 = *(const ulonglong2*)(W + (24 + u) * 8);
    ulonglong2 wo1 = *(const ulonglong2*)(W + (24 + u) * 8 + 4);

    float hv[8];
    #pragma unroll
    for (int j = 0; j < 8; j++) hv[j] = 0.f;
    float cu = 0.f;

    const float4* xsrc = (const float4*)g_xproj;
    const long long stride4 = (long long)B_ * 16;
    const long long step = dir ? -stride4 : stride4;
    long long idx = ((long long)(dir ? T_ - 1 : 0) * B_ + b) * 16 + dir * 8 + u;
    float4 buf[4];
    #pragma unroll
    for (int p = 0; p < 4; p++) buf[p] = xsrc[idx + p * step];

    float* hp0 = g_h + (size_t)b * 16 + dir * 8 + u;

    #pragma unroll 4
    for (int s = 0; s < T_; s++) {
        const int tt = dir ? (T_ - 1 - s) : s;
        float4 x = buf[s & 3];
        if (s + 4 < T_) buf[s & 3] = xsrc[idx + (long long)(s + 4) * step];

        ull h01 = pack2(hv[0], hv[1]), h23 = pack2(hv[2], hv[3]);
        ull h45 = pack2(hv[4], hv[5]), h67 = pack2(hv[6], hv[7]);

        float gi = dot8p(h01, h23, h45, h67, wi0, wi1, x.x);
        float gf = dot8p(h01, h23, h45, h67, wf0, wf1, x.y);
        float gg = dot8p(h01, h23, h45, h67, wg0, wg1, x.z);
        float go = dot8p(h01, h23, h45, h67, wo0, wo1, x.w);

        float ii = sigm_hw(gi), ff = sigm_hw(gf);
        float g2 = tanh_hw(gg), oo = sigm_hw(go);
        cu = __fmaf_rn(ff, cu, ii * g2);
        float hu = oo * tanh_hw(cu);
        #pragma unroll
        for (int j = 0; j < 8; j++)
            hv[j] = __shfl_sync(0xffffffffu, hu, base + j);
        hp0[(size_t)tt * (B_ * 16)] = hu;
    }
}

// ---------------- K3: ptr-LSTM input projection ----------------
__global__ void __launch_bounds__(256) zproj_kernel(
    const float* __restrict__ Wihp, const float* __restrict__ bip,
    const float* __restrict__ bhp)
{
    __shared__ float W[64][16];
    __shared__ float bias[64];
    const int tid = threadIdx.x;
    #pragma unroll
    for (int i = tid; i < 1024; i += 256) {
        int n = i >> 4, k = i & 15;
        int u = n >> 2, g = n & 3;
        W[n][k] = Wihp[(g * 16 + u) * 16 + k];
    }
    if (tid < 64) {
        int u = tid >> 2, g = tid & 3;
        int r = g * 16 + u;
        bias[tid] = bip[r] + bhp[r];
    }
    __syncthreads();

    size_t r = (size_t)blockIdx.x * 256 + tid;
    const float4* h4 = (const float4*)(g_h + r * 16);
    float4 a0 = h4[0], a1 = h4[1], a2 = h4[2], a3 = h4[3];
    float hr[16] = {a0.x, a0.y, a0.z, a0.w, a1.x, a1.y, a1.z, a1.w,
                    a2.x, a2.y, a2.z, a2.w, a3.x, a3.y, a3.z, a3.w};
    float* out = g_zproj + r * 64;
    #pragma unroll
    for (int g0 = 0; g0 < 64; g0 += 4) {
        float o[4];
        #pragma unroll
        for (int q = 0; q < 4; q++) {
            int g = g0 + q;
            float a = bias[g];
            #pragma unroll
            for (int k = 0; k < 16; k++) a = __fmaf_rn(W[g][k], hr[k], a);
            o[q] = a;
        }
        *(float4*)(out + g0) = make_float4(o[0], o[1], o[2], o[3]);
    }
}

// ---------------- K4: ptr LSTM scan (H=16) ----------------
__global__ void __launch_bounds__(64) lstm_ptr_kernel(const float* __restrict__ Whhp)
{
    const int tid = threadIdx.x;
    const int e = tid >> 4, u = tid & 15;
    const int b = blockIdx.x * 4 + e;
    const int base = tid & 16;

    ulonglong2 wi[4], wf4[4], wg4[4], wo4[4];
    {
        const ulonglong2* p;
        p = (const ulonglong2*)(Whhp + u * 16);
        wi[0] = p[0]; wi[1] = p[1]; wi[2] = p[2]; wi[3] = p[3];
        p = (const ulonglong2*)(Whhp + (16 + u) * 16);
        wf4[0] = p[0]; wf4[1] = p[1]; wf4[2] = p[2]; wf4[3] = p[3];
        p = (const ulonglong2*)(Whhp + (32 + u) * 16);
        wg4[0] = p[0]; wg4[1] = p[1]; wg4[2] = p[2]; wg4[3] = p[3];
        p = (const ulonglong2*)(Whhp + (48 + u) * 16);
        wo4[0] = p[0]; wo4[1] = p[1]; wo4[2] = p[2]; wo4[3] = p[3];
    }

    float hv[16];
    #pragma unroll
    for (int j = 0; j < 16; j++) hv[j] = 0.f;
    float cu = 0.f;

    const float4* zsrc = (const float4*)g_zproj;
    const long long stride4 = (long long)B_ * 16;
    long long idx = (long long)b * 16 + u;
    float4 buf[4];
    #pragma unroll
    for (int p = 0; p < 4; p++) buf[p] = zsrc[idx + p * stride4];

    float* zp0 = g_z + (size_t)b * 16 + u;

    #pragma unroll 4
    for (int t = 0; t < T_; t++) {
        float4 x = buf[t & 3];
        if (t + 4 < T_) buf[t & 3] = zsrc[idx + (long long)(t + 4) * stride4];

        ull hp[8];
        #pragma unroll
        for (int j = 0; j < 8; j++) hp[j] = pack2(hv[2 * j], hv[2 * j + 1]);

        float gi = dot16p(hp, wi,  x.x);
        float gf = dot16p(hp, wf4, x.y);
        float gg = dot16p(hp, wg4, x.z);
        float go = dot16p(hp, wo4, x.w);

        float ii = sigm_hw(gi), ff = sigm_hw(gf);
        float g2 = tanh_hw(gg), oo = sigm_hw(go);
        cu = __fmaf_rn(ff, cu, ii * g2);
        float hu = oo * tanh_hw(cu);
        #pragma unroll
        for (int j = 0; j < 16; j++)
            hv[j] = __shfl_sync(0xffffffffu, hu, base + j);
        zp0[(size_t)t * (B_ * 16)] = hu;
    }
}

// ---------------- K5: fully-fused MMA attention + output head, one CTA per t -------
// Per 64-column chunk: S = H Z^T via bf16 hi/lo MMA, exp in C-fragments (reused
// directly as A-fragments of the ctx GEMM), per-chunk complete colsum (softmax
// axis = b lives entirely in this CTA), cinv folded into Hst = cinv*h (bf16 hi/lo),
// ctx accumulated in C-fragments across chunks. No gmem exp cache.
#define AT_SA_HI 0
#define AT_SA_LO 24576
#define AT_SZ_HI 49152
#define AT_SZ_LO 52224
#define AT_HST_HI 55296
#define AT_HST_LO 57600
#define AT_PART 59904
#define AT_WH 64000
#define AT_WE 65024
#define AT_WV 66048
#define AT_CTX 66112
#define ATT_SMEM (AT_CTX + 32768)   // 98880 bytes

__global__ void __launch_bounds__(512, 1) attn_kernel(
    const float* __restrict__ W_h, const float* __restrict__ W_e,
    const float* __restrict__ W_v, float* __restrict__ out)
{
    extern __shared__ __align__(1024) char attsm[];
    char* s = attsm;
    const uint32_t sb = smem_u32(attsm);
    const int tid = threadIdx.x;
    const int w = tid >> 5, lane = tid & 31;
    const int t = blockIdx.x;

    // prologue: H rows -> bf16 hi/lo smem tiles (48B-padded rows)
    {
        const float4* hr = (const float4*)(g_h + ((size_t)t * B_ + tid) * 16);
        float4 h0 = hr[0], h1 = hr[1], h2 = hr[2], h3 = hr[3];
        uint4 hiA, loA, hiB, loB;
        cvt_hilo8(h0, h1, hiA, loA);
        cvt_hilo8(h2, h3, hiB, loB);
        *(uint4*)(s + AT_SA_HI + tid * 48)      = hiA;
        *(uint4*)(s + AT_SA_HI + tid * 48 + 16) = hiB;
        *(uint4*)(s + AT_SA_LO + tid * 48)      = loA;
        *(uint4*)(s + AT_SA_LO + tid * 48 + 16) = loB;
    }
    if (tid < 256) {
        ((float*)(s + AT_WH))[tid] = W_h[tid];
        ((float*)(s + AT_WE))[tid] = W_e[tid];
    }
    if (tid < 16) ((float*)(s + AT_WV))[tid] = W_v[tid];

    float ctxf[2][2][4];
    #pragma unroll
    for (int mt = 0; mt < 2; mt++)
        #pragma unroll
        for (int dt = 0; dt < 2; dt++)
            #pragma unroll
            for (int k = 0; k < 4; k++) ctxf[mt][dt][k] = 0.f;

    const uint32_t aoff0 = (uint32_t)(32 * w + (lane & 15)) * 48 + (uint32_t)(lane >> 4) * 16;
    const uint32_t zoffB = (uint32_t)(lane & 7) * 48 + (uint32_t)((lane >> 3) & 1) * 16;
    const uint32_t hoffB = (uint32_t)(lane & 7) * 144 + (uint32_t)((lane >> 3) & 1) * 16;

    for (int ch = 0; ch < 8; ch++) {
        // 1. stage z chunk (pre-scaled by log2 e), bf16 hi/lo
        if (tid < 64) {
            const float L2E = 1.44269504f;
            const float4* zr = (const float4*)(g_z + ((size_t)t * B_ + ch * 64 + tid) * 16);
            float4 z0 = zr[0], z1 = zr[1], z2 = zr[2], z3 = zr[3];
            z0.x *= L2E; z0.y *= L2E; z0.z *= L2E; z0.w *= L2E;
            z1.x *= L2E; z1.y *= L2E; z1.z *= L2E; z1.w *= L2E;
            z2.x *= L2E; z2.y *= L2E; z2.z *= L2E; z2.w *= L2E;
            z3.x *= L2E; z3.y *= L2E; z3.z *= L2E; z3.w *= L2E;
            uint4 hiA, loA, hiB, loB;
            cvt_hilo8(z0, z1, hiA, loA);
            cvt_hilo8(z2, z3, hiB, loB);
            *(uint4*)(s + AT_SZ_HI + tid * 48)      = hiA;
            *(uint4*)(s + AT_SZ_HI + tid * 48 + 16) = hiB;
            *(uint4*)(s + AT_SZ_LO + tid * 48)      = loA;
            *(uint4*)(s + AT_SZ_LO + tid * 48 + 16) = loB;
        }
        __syncthreads();

        // 2-4. S-MMA + exp + pack E fragments + colsum partials
        uint32_t Ae[2][4][4];
        float cs[8][2];
        #pragma unroll
        for (int nt = 0; nt < 8; nt++) { cs[nt][0] = 0.f; cs[nt][1] = 0.f; }

        #pragma unroll
        for (int mt = 0; mt < 2; mt++) {
            uint32_t ahi[4], alo[4];
            ldm4(ahi, sb + AT_SA_HI + aoff0 + mt * 768);
            ldm4(alo, sb + AT_SA_LO + aoff0 + mt * 768);
            #pragma unroll
            for (int p = 0; p < 4; p++) {
                #pragma unroll
                for (int hf = 0; hf < 2; hf++) {
                    const int nt = 2 * p + hf;
                    uint32_t bh[2], bl[2];
                    ldm2(bh, sb + AT_SZ_HI + zoffB + nt * 384);
                    ldm2(bl, sb + AT_SZ_LO + zoffB + nt * 384);
                    float c[4] = {0.f, 0.f, 0.f, 0.f};
                    mma_bf16(c, ahi, bh[0], bh[1]);
                    mma_bf16(c, ahi, bl[0], bl[1]);
                    mma_bf16(c, alo, bh[0], bh[1]);
                    uint32_t p01 = cvt2(ex2(c[1]), ex2(c[0]));
                    uint32_t p23 = cvt2(ex2(c[3]), ex2(c[2]));
                    Ae[mt][p][2 * hf]     = p01;
                    Ae[mt][p][2 * hf + 1] = p23;
                    cs[nt][0] += flo(p01) + flo(p23);
                    cs[nt][1] += fhi(p01) + fhi(p23);
                }
            }
        }
        #pragma unroll
        for (int nt = 0; nt < 8; nt++) {
            float s0 = cs[nt][0], s1 = cs[nt][1];
            s0 += __shfl_xor_sync(0xffffffffu, s0, 4);
            s1 += __shfl_xor_sync(0xffffffffu, s1, 4);
            s0 += __shfl_xor_sync(0xffffffffu, s0, 8);
            s1 += __shfl_xor_sync(0xffffffffu, s1, 8);
            s0 += __shfl_xor_sync(0xffffffffu, s0, 16);
            s1 += __shfl_xor_sync(0xffffffffu, s1, 16);
            if (lane < 4)
                *(float2*)(s + AT_PART + w * 256 + (nt * 8 + 2 * lane) * 4) = make_float2(s0, s1);
        }
        __syncthreads();

        // 5. final colsum + build Hst = cinv * h (transposed, bf16 hi/lo)
        if (tid < 64) {
            float sum = 0.f;
            #pragma unroll
            for (int ww = 0; ww < 16; ww++)
                sum += *(const float*)(s + AT_PART + ww * 256 + tid * 4);
            float ci = __fdividef(1.f, sum);
            const int cg = ch * 64 + tid;   // global row index for h
            const uint32_t* rh = (const uint32_t*)(s + AT_SA_HI + cg * 48);
            const uint32_t* rl = (const uint32_t*)(s + AT_SA_LO + cg * 48);
            #pragma unroll
            for (int i = 0; i < 8; i++) {
                uint32_t uh = rh[i], ul = rl[i];
                float h0 = flo(uh) + flo(ul);
                float h1 = fhi(uh) + fhi(ul);
                float s0v = h0 * ci, s1v = h1 * ci;
                uint32_t hp = cvt2(s1v, s0v);
                float r0 = s0v - flo(hp);
                float r1 = s1v - fhi(hp);
                uint32_t lp = cvt2(r1, r0);
                *(unsigned short*)(s + AT_HST_HI + (2 * i) * 144 + tid * 2)     = (unsigned short)(hp & 0xffffu);
                *(unsigned short*)(s + AT_HST_HI + (2 * i + 1) * 144 + tid * 2) = (unsigned short)(hp >> 16);
                *(unsigned short*)(s + AT_HST_LO + (2 * i) * 144 + tid * 2)     = (unsigned short)(lp & 0xffffu);
                *(unsigned short*)(s + AT_HST_LO + (2 * i + 1) * 144 + tid * 2) = (unsigned short)(lp >> 16);
            }
        }
        __syncthreads();

        // 6. ctx += E @ Hst  (E fragments reused directly as A operands)
        #pragma unroll
        for (int ks = 0; ks < 4; ks++) {
            #pragma unroll
            for (int dt = 0; dt < 2; dt++) {
                uint32_t bh[2], bl[2];
                ldm2(bh, sb + AT_HST_HI + hoffB + dt * 1152 + ks * 32);
                ldm2(bl, sb + AT_HST_LO + hoffB + dt * 1152 + ks * 32);
                mma_bf16(ctxf[0][dt], Ae[0][ks], bh[0], bh[1]);
                mma_bf16(ctxf[0][dt], Ae[0][ks], bl[0], bl[1]);
                mma_bf16(ctxf[1][dt], Ae[1][ks], bh[0], bh[1]);
                mma_bf16(ctxf[1][dt], Ae[1][ks], bl[0], bl[1]);
            }
        }
        __syncthreads();
    }

    // epilogue: ctx fragments -> smem
    #pragma unroll
    for (int mt = 0; mt < 2; mt++)
        #pragma unroll
        for (int dt = 0; dt < 2; dt++) {
            const int r0 = 32 * w + 16 * mt + (lane >> 2);
            const int col = 8 * dt + 2 * (lane & 3);
            *(float2*)(s + AT_CTX + (r0 * 16 + col) * 4) =
                make_float2(ctxf[mt][dt][0], ctxf[mt][dt][1]);
            *(float2*)(s + AT_CTX + ((r0 + 8) * 16 + col) * 4) =
                make_float2(ctxf[mt][dt][2], ctxf[mt][dt][3]);
        }
    __syncthreads();

    // output head (per thread = one b row)
    {
        float hbv[16], ctxv[16];
        const uint32_t* rh = (const uint32_t*)(s + AT_SA_HI + tid * 48);
        const uint32_t* rl = (const uint32_t*)(s + AT_SA_LO + tid * 48);
        #pragma unroll
        for (int i = 0; i < 8; i++) {
            uint32_t uh = rh[i], ul = rl[i];
            hbv[2 * i]     = flo(uh) + flo(ul);
            hbv[2 * i + 1] = fhi(uh) + fhi(ul);
        }
        const float4* cx = (const float4*)(s + AT_CTX + tid * 64);
        float4 c0 = cx[0], c1 = cx[1], c2 = cx[2], c3 = cx[3];
        ctxv[0] = c0.x;  ctxv[1] = c0.y;  ctxv[2] = c0.z;  ctxv[3] = c0.w;
        ctxv[4] = c1.x;  ctxv[5] = c1.y;  ctxv[6] = c1.z;  ctxv[7] = c1.w;
        ctxv[8] = c2.x;  ctxv[9] = c2.y;  ctxv[10] = c2.z; ctxv[11] = c2.w;
        ctxv[12] = c3.x; ctxv[13] = c3.y; ctxv[14] = c3.z; ctxv[15] = c3.w;

        const float* whs = (const float*)(s + AT_WH);
        const float* wes = (const float*)(s + AT_WE);
        const float* wvs = (const float*)(s + AT_WV);
        float pacc = 0.f;
        #pragma unroll
        for (int d = 0; d < 16; d++) {
            float a = 0.f;
            #pragma unroll
            for (int k = 0; k < 16; k++) a = __fmaf_rn(whs[d * 16 + k], hbv[k], a);
            #pragma unroll
            for (int k = 0; k < 16; k++) a = __fmaf_rn(wes[d * 16 + k], ctxv[k], a);
            float ud = tanh_hw(a);
            pacc = __fmaf_rn(ud, wvs[d], pacc);
        }
        out[(size_t)t * B_ + tid] = sigm_hw(pacc);
    }
}

// ---------------- launch ----------------
extern "C" void kernel_launch(void* const* d_in, const int* in_sizes, int n_in,
                              void* d_out, int out_size)
{
    (void)in_sizes; (void)n_in; (void)out_size;
    const float* X     = (const float*)d_in[0];
    const float* Wih_f = (const float*)d_in[1];
    const float* Whh_f = (const float*)d_in[2];
    const float* bih_f = (const float*)d_in[3];
    const float* bhh_f = (const float*)d_in[4];
    const float* Wih_b = (const float*)d_in[5];
    const float* Whh_b = (const float*)d_in[6];
    const float* bih_b = (const float*)d_in[7];
    const float* bhh_b = (const float*)d_in[8];
    const float* Wih_p = (const float*)d_in[9];
    const float* Whh_p = (const float*)d_in[10];
    const float* bih_p = (const float*)d_in[11];
    const float* bhh_p = (const float*)d_in[12];
    const float* W_h   = (const float*)d_in[13];
    const float* W_e   = (const float*)d_in[14];
    const float* W_v   = (const float*)d_in[15];
    float* out = (float*)d_out;

    cudaFuncSetAttribute(proj_mma_kernel, cudaFuncAttributeMaxDynamicSharedMemorySize, PROJ_SMEM);
    proj_mma_kernel<<<R_ / 128, 256, PROJ_SMEM>>>(X, Wih_f, Wih_b, bih_f, bhh_f, bih_b, bhh_b);

    lstm_bi_kernel<<<dim3(64, 2), 64>>>(Whh_f, Whh_b);
    zproj_kernel<<<256, 256>>>(Wih_p, bih_p, bhh_p);
    lstm_ptr_kernel<<<128, 64>>>(Whh_p);

    cudaFuncSetAttribute(attn_kernel, cudaFuncAttributeMaxDynamicSharedMemorySize, ATT_SMEM);
    attn_kernel<<<128, 512, ATT_SMEM>>>(W_h, W_e, W_v, out);
}